// round 8
// baseline (speedup 1.0000x reference)
#include <cuda_runtime.h>
#include <stdint.h>

// RoPE: x (B,H,S,128) fp32, token_positions (S,) int32,
// cos_table/sin_table (8192, 64) fp32.
//
// Same schedule as R7 (grid-stride UN=4, bulk+tail). Cache policy combo:
//   x loads : __ldcs (evict_first fills -> warm x set from prior replays
//             stays L2-resident; miss fills evict each other)
//   stores  : __stwt (write-through, no L2 allocation -> write stream
//             cannot churn the evict_first pool)
// Goal: raise cross-replay L2 hit-rate on x from the random-replacement
// steady state (~37%) toward the resident-set bound (~90%).

#define THREADS 256
#define UN 4

template<bool POW2>
__global__ void __launch_bounds__(THREADS)
rope_bulk(const float4* __restrict__ x,
          const int*    __restrict__ tok_pos,
          const float2* __restrict__ cos_t,   // row stride 32 float2
          const float2* __restrict__ sin_t,
          float4*       __restrict__ out,
          int seq, int seq_mask)
{
    const int stride = gridDim.x * blockDim.x;
    const int base   = blockIdx.x * blockDim.x + threadIdx.x;

    // Batch 1: 4 independent x loads, evict_first fills
    float4 v[UN];
#pragma unroll
    for (int k = 0; k < UN; k++)
        v[k] = __ldcs(&x[base + k * stride]);

    // Batch 2: token positions (normal caching)
    int p[UN];
#pragma unroll
    for (int k = 0; k < UN; k++) {
        int row = (base + k * stride) >> 5;    // 32 float4 per 128-elem row
        int pos = POW2 ? (row & seq_mask) : (row % seq);
        p[k] = __ldg(&tok_pos[pos]);
    }

    // Batch 3: table gathers (L2-resident, warp-coalesced)
    float2 c[UN], s[UN];
#pragma unroll
    for (int k = 0; k < UN; k++) {
        int q = (base + k * stride) & 31;
        c[k] = __ldg(&cos_t[p[k] * 32 + q]);
        s[k] = __ldg(&sin_t[p[k] * 32 + q]);
    }

    // Compute + write-through stores (no L2 allocation)
#pragma unroll
    for (int k = 0; k < UN; k++) {
        float4 o;
        o.x = fmaf(c[k].x, v[k].x, -s[k].x * v[k].y);
        o.y = fmaf(s[k].x, v[k].x,  c[k].x * v[k].y);
        o.z = fmaf(c[k].y, v[k].z, -s[k].y * v[k].w);
        o.w = fmaf(s[k].y, v[k].z,  c[k].y * v[k].w);
        __stwt(&out[base + k * stride], o);
    }
}

template<bool POW2>
__global__ void __launch_bounds__(THREADS)
rope_tail(const float4* __restrict__ x,
          const int*    __restrict__ tok_pos,
          const float2* __restrict__ cos_t,
          const float2* __restrict__ sin_t,
          float4*       __restrict__ out,
          int start, int n4, int seq, int seq_mask)
{
    int i = start + blockIdx.x * blockDim.x + threadIdx.x;
    if (i >= n4) return;
    int row = i >> 5;
    int q   = i & 31;
    int pos = POW2 ? (row & seq_mask) : (row % seq);
    int p   = __ldg(&tok_pos[pos]);
    float2 c = __ldg(&cos_t[p * 32 + q]);
    float2 s = __ldg(&sin_t[p * 32 + q]);
    float4 v = __ldcs(&x[i]);
    float4 o;
    o.x = fmaf(c.x, v.x, -s.x * v.y);
    o.y = fmaf(s.x, v.x,  c.x * v.y);
    o.z = fmaf(c.y, v.z, -s.y * v.w);
    o.w = fmaf(s.y, v.z,  c.y * v.w);
    __stwt(&out[i], o);
}

extern "C" void kernel_launch(void* const* d_in, const int* in_sizes, int n_in,
                              void* d_out, int out_size)
{
    const float4* x     = (const float4*)d_in[0];
    const int*    tpos  = (const int*)   d_in[1];
    const float2* cos_t = (const float2*)d_in[2];
    const float2* sin_t = (const float2*)d_in[3];
    float4*       out   = (float4*)      d_out;

    int seq = in_sizes[1];
    int n4  = out_size / 4;

    const int chunk  = THREADS * UN;
    int  blocks = n4 / chunk;           // bulk covers blocks*chunk exactly
    int  n_bulk = blocks * chunk;
    int  tail   = n4 - n_bulk;
    bool pow2   = (seq & (seq - 1)) == 0;

    if (blocks > 0) {
        if (pow2)
            rope_bulk<true ><<<blocks, THREADS>>>(x, tpos, cos_t, sin_t, out,
                                                  seq, seq - 1);
        else
            rope_bulk<false><<<blocks, THREADS>>>(x, tpos, cos_t, sin_t, out,
                                                  seq, 0);
    }
    if (tail > 0) {
        int tblocks = (tail + THREADS - 1) / THREADS;
        if (pow2)
            rope_tail<true ><<<tblocks, THREADS>>>(x, tpos, cos_t, sin_t, out,
                                                   n_bulk, n4, seq, seq - 1);
        else
            rope_tail<false><<<tblocks, THREADS>>>(x, tpos, cos_t, sin_t, out,
                                                   n_bulk, n4, seq, 0);
    }
}

// round 9
// speedup vs baseline: 1.0412x; 1.0412x over previous
#include <cuda_runtime.h>
#include <stdint.h>

// RoPE: x (B,H,S,128) fp32, token_positions (S,) int32,
// cos_table/sin_table (8192, 64) fp32.
//
// Consolidated best configuration (R2-R8 sweep):
//  - block-contiguous CHUNK with compile-time immediate offsets (R4)
//  - default-cached x loads, __stwt stores (R7)
//  - UN=4 (MLP sweet spot), __launch_bounds__(256,6)
// The op is pinned at the mixed read/write HBM ceiling (~75% of spec);
// this config minimizes issue overhead at that ceiling.

#define THREADS 256
#define UN 4
#define CHUNK (THREADS * UN)           // 1024 float4 per CTA

template<bool POW2>
__global__ void __launch_bounds__(THREADS, 6)
rope_bulk(const float4* __restrict__ x,
          const int*    __restrict__ tok_pos,
          const float2* __restrict__ cos_t,   // row stride 32 float2
          const float2* __restrict__ sin_t,
          float4*       __restrict__ out,
          int seq, int seq_mask)
{
    const int t    = threadIdx.x;
    const int base = blockIdx.x * CHUNK + t;
    const float4* __restrict__ xp = x   + base;
    float4*       __restrict__ op = out + base;

    // Batch 1: 4 independent 16B loads at immediate offsets
    float4 v[UN];
#pragma unroll
    for (int k = 0; k < UN; k++)
        v[k] = xp[k * THREADS];

    // Batch 2: token positions (uniform per warp; tiny, cache-resident)
    const int q    = t & 31;            // float4 col within 128-elem row
    const int row0 = base >> 5;
    int p[UN];
#pragma unroll
    for (int k = 0; k < UN; k++) {
        int row = row0 + k * (THREADS / 32);
        int pos = POW2 ? (row & seq_mask) : (row % seq);
        p[k] = __ldg(&tok_pos[pos]);
    }

    // Batch 3: table gathers (L2-resident, warp-coalesced 256B)
    float2 c[UN], s[UN];
#pragma unroll
    for (int k = 0; k < UN; k++) {
        c[k] = __ldg(&cos_t[p[k] * 32 + q]);
        s[k] = __ldg(&sin_t[p[k] * 32 + q]);
    }

    // Compute + write-through stores at immediate offsets
#pragma unroll
    for (int k = 0; k < UN; k++) {
        float4 o;
        o.x = fmaf(c[k].x, v[k].x, -s[k].x * v[k].y);
        o.y = fmaf(s[k].x, v[k].x,  c[k].x * v[k].y);
        o.z = fmaf(c[k].y, v[k].z, -s[k].y * v[k].w);
        o.w = fmaf(s[k].y, v[k].z,  c[k].y * v[k].w);
        __stwt(&op[k * THREADS], o);
    }
}

// Tail (only launches if n4 % CHUNK != 0; never for the bench shape).
template<bool POW2>
__global__ void __launch_bounds__(THREADS)
rope_tail(const float4* __restrict__ x,
          const int*    __restrict__ tok_pos,
          const float2* __restrict__ cos_t,
          const float2* __restrict__ sin_t,
          float4*       __restrict__ out,
          int start, int n4, int seq, int seq_mask)
{
    int i = start + blockIdx.x * blockDim.x + threadIdx.x;
    if (i >= n4) return;
    int row = i >> 5;
    int q   = i & 31;
    int pos = POW2 ? (row & seq_mask) : (row % seq);
    int p   = __ldg(&tok_pos[pos]);
    float2 c = __ldg(&cos_t[p * 32 + q]);
    float2 s = __ldg(&sin_t[p * 32 + q]);
    float4 v = x[i];
    float4 o;
    o.x = fmaf(c.x, v.x, -s.x * v.y);
    o.y = fmaf(s.x, v.x,  c.x * v.y);
    o.z = fmaf(c.y, v.z, -s.y * v.w);
    o.w = fmaf(s.y, v.z,  c.y * v.w);
    __stwt(&out[i], o);
}

extern "C" void kernel_launch(void* const* d_in, const int* in_sizes, int n_in,
                              void* d_out, int out_size)
{
    const float4* x     = (const float4*)d_in[0];
    const int*    tpos  = (const int*)   d_in[1];
    const float2* cos_t = (const float2*)d_in[2];
    const float2* sin_t = (const float2*)d_in[3];
    float4*       out   = (float4*)      d_out;

    int seq = in_sizes[1];
    int n4  = out_size / 4;

    int  blocks = n4 / CHUNK;
    int  n_bulk = blocks * CHUNK;
    int  tail   = n4 - n_bulk;
    bool pow2   = (seq & (seq - 1)) == 0;

    if (blocks > 0) {
        if (pow2)
            rope_bulk<true ><<<blocks, THREADS>>>(x, tpos, cos_t, sin_t, out,
                                                  seq, seq - 1);
        else
            rope_bulk<false><<<blocks, THREADS>>>(x, tpos, cos_t, sin_t, out,
                                                  seq, 0);
    }
    if (tail > 0) {
        int tblocks = (tail + THREADS - 1) / THREADS;
        if (pow2)
            rope_tail<true ><<<tblocks, THREADS>>>(x, tpos, cos_t, sin_t, out,
                                                   n_bulk, n4, seq, seq - 1);
        else
            rope_tail<false><<<tblocks, THREADS>>>(x, tpos, cos_t, sin_t, out,
                                                   n_bulk, n4, seq, 0);
    }
}